// round 10
// baseline (speedup 1.0000x reference)
#include <cuda_runtime.h>
#include <math.h>
#include <stdint.h>

#define K_COMP 8192
#define N_SAMP 8192
#define B_X    2048
#define D_W    13

#define LOG_2PI 1.8378770664093453f
#define L2E     1.4426950408889634f

#define NRB   (N_SAMP / 16)     // 512 row-blocks of 16 samples
#define NNB   (K_COMP / 8)      // 1024 col-blocks of 8 components
#define NC    8                 // n-chunks
#define NB_PC (NNB / NC)        // 128 col-blocks per chunk

#define LSE_BLOCKS (NC * 64)            // 512  (first in grid: longest blocks)
#define REG_BLOCKS (N_SAMP / 8)         // 1024 (8 warps/block, 1 sample/warp)
#define RED_BLOCKS 32

// ---------------- scratch (no allocations allowed) ----------------
__device__ float  g_w16[N_SAMP * 16];     // fp32 w, padded k=13..15 = 0
__device__ float  g_wn[N_SAMP];           // ||w||^2 (fp32 exact)
__device__ float4 g_gu[K_COMP / 2];       // (g0,g1,u0,u1) per col-pair
__device__ uint4  g_Afrag[NRB * 32];      // per-lane A fragments (bf16x2 x4)
__device__ uint2  g_Bfrag[NNB * 32];      // per-lane B fragments (bf16x2 x2)
__device__ float  g_dsum[N_SAMP];         // sum_b (y_pred - y)^2
__device__ float  g_SP[NC][N_SAMP];       // per-chunk partial exp-sums
__device__ double g_part[RED_BLOCKS][3];  // per-block (q, wn, dsum) sums
__device__ unsigned g_ticket;             // last-block ticket (self-resetting)

__device__ __forceinline__ float tanh_fast(float x) {
    float r; asm("tanh.approx.f32 %0, %1;" : "=f"(r) : "f"(x)); return r;
}
__device__ __forceinline__ float exp2_fast(float x) {
    float r; asm("ex2.approx.f32 %0, %1;" : "=f"(r) : "f"(x)); return r;
}
// pack two f32 -> bf16x2, lo in low 16 bits
__device__ __forceinline__ unsigned packbf(float lo, float hi) {
    unsigned r; asm("cvt.rn.bf16x2.f32 %0, %1, %2;" : "=r"(r) : "f"(hi), "f"(lo)); return r;
}

// ---------------- kernel 1: ALL prep (block-range split) ----------------
// blocks [0, 32): per-sample w/norm/A-frags     (256 samples per block)
// blocks [32, 32+132): per-component g,u + B-frags (flat index)
__global__ __launch_bounds__(256) void prep_all(const float* __restrict__ emp,
                                                const float* __restrict__ rhos,
                                                const float* __restrict__ eps,
                                                const int* __restrict__ idxs) {
    if (blockIdx.x < 32) {
        __shared__ float sw[256][16];
        int tid = threadIdx.x;
        int s = blockIdx.x * 256 + tid;

        int idx = idxs[s];
        float rho = rhos[idx];
        float sd = (rho > 20.f) ? rho : log1pf(__expf(rho));
        float wn = 0.f;
#pragma unroll
        for (int d = 0; d < 16; d++) {
            float w = 0.f;
            if (d < D_W) w = fmaf(__ldg(&eps[s * D_W + d]), sd, __ldg(&emp[idx * D_W + d]));
            sw[tid][d] = w;
            g_w16[s * 16 + d] = w;
            wn = fmaf(w, w, wn);
        }
        g_wn[s] = wn;
        __syncthreads();

        // A fragments (m16n8k16 row.col A layout), 16 row-blocks per block
        int rb0 = blockIdx.x * 16;
#pragma unroll
        for (int h = 0; h < 2; h++) {
            int e = h * 256 + tid;             // 0..511
            int rbl = e >> 5;
            int lane = e & 31, gid = lane >> 2, tg = lane & 3;
            const float* w0 = sw[rbl * 16 + gid];
            const float* w8 = sw[rbl * 16 + gid + 8];
            int k0 = tg * 2;
            uint4 r;
            r.x = packbf(w0[k0], w0[k0 + 1]);
            r.y = packbf(w8[k0], w8[k0 + 1]);
            r.z = packbf(w0[k0 + 8], w0[k0 + 9]);
            r.w = packbf(w8[k0 + 8], w8[k0 + 9]);
            g_Afrag[(rb0 + rbl) * 32 + lane] = r;
        }
    } else {
        int tid = (blockIdx.x - 32) * 256 + threadIdx.x;
        if (tid < K_COMP) {
            int k = tid;
            float rho = rhos[k];
            float sd = (rho > 20.f) ? rho : log1pf(__expf(rho));   // softplus
            float var = sd * sd;
            float inv = 1.f / var;
            float en = 0.f;
#pragma unroll
            for (int d = 0; d < D_W; d++) {
                float v = __ldg(&emp[k * D_W + d]);
                en = fmaf(v, v, en);
            }
            float c = -0.5f * ((float)D_W * LOG_2PI + (float)D_W * logf(var));
            float g = L2E * inv;
            float u = L2E * (c - 0.5f * inv * en);
            float* gu = (float*)&g_gu[k >> 1];
            gu[(k & 1) + 0] = g;
            gu[(k & 1) + 2] = u;
        } else if (tid < K_COMP + NNB * 32) {
            // B fragments: m16n8k16 row.col B layout (n=gid, k=2tg.. / +8)
            int t2 = tid - K_COMP;
            int lane = t2 & 31, gid = lane >> 2, tg = lane & 3;
            int nb = t2 >> 5;
            int n = nb * 8 + gid;
            int k0 = tg * 2;
            float e0 = __ldg(&emp[n * D_W + k0]);
            float e1 = __ldg(&emp[n * D_W + k0 + 1]);
            float e2 = (k0 + 8 < D_W) ? __ldg(&emp[n * D_W + k0 + 8]) : 0.f;
            float e3 = (k0 + 9 < D_W) ? __ldg(&emp[n * D_W + k0 + 9]) : 0.f;
            uint2 r;
            r.x = packbf(e0, e1);
            r.y = packbf(e2, e3);
            g_Bfrag[t2] = r;
        }
    }
}

// ---------------- kernel 2: FUSED tensor-core lse + regression ----------------
// blocks [0, LSE_BLOCKS): mma + exp2 sum. The whole B chunk (Bfrag 32KB +
//   gu 8KB) is staged in smem ONCE per block — all 8 warps stream it from LDS
//   instead of L2 (cuts ~400MB of L2 reads to ~50MB; L2 was at ~84% of cap).
// blocks [LSE_BLOCKS, +REG_BLOCKS): regression (MUFU tanh), uses smem for xy.
__global__ __launch_bounds__(256, 4) void fused_main(const float* __restrict__ x,
                                                     const float* __restrict__ y) {
    __shared__ __align__(16) unsigned char smem_raw[NB_PC * 32 * 8 + NB_PC * 4 * 16]; // 40KB

    if (blockIdx.x < LSE_BLOCKS) {
        uint2*  sB  = (uint2*)smem_raw;                       // [NB_PC*32]
        float4* sGU = (float4*)(smem_raw + NB_PC * 32 * 8);   // [NB_PC*4]

        int bid = blockIdx.x;                   // 0..511
        int tid = threadIdx.x;
        int wid = tid >> 5, lane = tid & 31;
        int gid = lane >> 2, tg = lane & 3;
        int chunk = bid >> 6;                   // 0..7
        int grp   = bid & 63;
        int rb = grp * 8 + wid;                 // 0..511
        int s0 = rb * 16;
        int nb0 = chunk * NB_PC;

        // stage chunk into smem (coalesced 8B/16B copies)
        for (int i = tid; i < NB_PC * 32; i += 256) sB[i] = g_Bfrag[nb0 * 32 + i];
        for (int i = tid; i < NB_PC * 4; i += 256)  sGU[i] = g_gu[nb0 * 4 + i];

        uint4 af = g_Afrag[rb * 32 + lane];
        float hw0 = -0.5f * g_wn[s0 + gid];
        float hw8 = -0.5f * g_wn[s0 + gid + 8];
        float S0 = 0.f, S8 = 0.f;
        __syncthreads();

#pragma unroll 4
        for (int i = 0; i < NB_PC; i++) {
            uint2 bf = sB[i * 32 + lane];       // LDS.64, conflict-free
            float4 gu = sGU[i * 4 + tg];        // LDS.128, quad-broadcast
            float c0 = hw0, c1 = hw0, c2 = hw8, c3 = hw8;
            asm volatile(
                "mma.sync.aligned.m16n8k16.row.col.f32.bf16.bf16.f32 "
                "{%0,%1,%2,%3}, {%4,%5,%6,%7}, {%8,%9}, {%0,%1,%2,%3};"
                : "+f"(c0), "+f"(c1), "+f"(c2), "+f"(c3)
                : "r"(af.x), "r"(af.y), "r"(af.z), "r"(af.w),
                  "r"(bf.x), "r"(bf.y));
            // t = g*(dot - 0.5||w||^2) + u  (base-2, unshifted; always < 0)
            S0 += exp2_fast(fmaf(gu.x, c0, gu.z));
            S0 += exp2_fast(fmaf(gu.y, c1, gu.w));
            S8 += exp2_fast(fmaf(gu.x, c2, gu.z));
            S8 += exp2_fast(fmaf(gu.y, c3, gu.w));
        }

        S0 += __shfl_xor_sync(0xffffffffu, S0, 1);
        S0 += __shfl_xor_sync(0xffffffffu, S0, 2);
        S8 += __shfl_xor_sync(0xffffffffu, S8, 1);
        S8 += __shfl_xor_sync(0xffffffffu, S8, 2);
        if (tg == 0) {
            g_SP[chunk][s0 + gid]     = S0;
            g_SP[chunk][s0 + gid + 8] = S8;
        }
    } else {
        float2* sxy = (float2*)smem_raw;        // [B_X] = 16KB

        int bid = blockIdx.x - LSE_BLOCKS;      // 0..1023
        int tid = threadIdx.x;
        for (int i = tid; i < B_X; i += 256)
            sxy[i] = make_float2(x[i], y[i]);
        __syncthreads();

        int wid = tid >> 5, lane = tid & 31;
        int s = bid * 8 + wid;

        float wd = (lane < D_W) ? g_w16[s * 16 + lane] : 0.f;
        float p[D_W];
#pragma unroll
        for (int d = 0; d < D_W; d++) p[d] = __shfl_sync(0xffffffffu, wd, d);
        float w10 = p[0], w11 = p[1], b10 = p[2], b11 = p[3];
        float w200 = p[4], w201 = p[5], w210 = p[6], w211 = p[7];
        float b20 = p[8], b21 = p[9], w30 = p[10], w31 = p[11], b3 = p[12];

        float acc = 0.f;
#pragma unroll 8
        for (int t = 0; t < B_X / 32; t++) {
            float2 xy = sxy[t * 32 + lane];
            float h0 = tanh_fast(fmaf(w10, xy.x, b10));
            float h1 = tanh_fast(fmaf(w11, xy.x, b11));
            float z0 = tanh_fast(fmaf(w200, h0, fmaf(w201, h1, b20)));
            float z1 = tanh_fast(fmaf(w210, h0, fmaf(w211, h1, b21)));
            float yp = fmaf(w30, z0, fmaf(w31, z1, b3));
            float d = yp - xy.y;
            acc = fmaf(d, d, acc);
        }
#pragma unroll
        for (int o = 16; o; o >>= 1) acc += __shfl_xor_sync(0xffffffffu, acc, o);
        if (lane == 0) g_dsum[s] = acc;
    }
}

// ---------------- kernel 3: reduction + final (last-block pattern) ----------------
__global__ __launch_bounds__(256) void reduce_final(float* __restrict__ out) {
    __shared__ double sh[3][8];
    int tid = threadIdx.x;
    int s = blockIdx.x * 256 + tid;

    float S = 0.f;
#pragma unroll
    for (int c = 0; c < NC; c++) S += g_SP[c][s];
    double q  = (double)__logf(S);
    double wn = (double)g_wn[s];
    double ds = (double)g_dsum[s];

    int lane = tid & 31, warp = tid >> 5;
#pragma unroll
    for (int o = 16; o; o >>= 1) {
        q  += __shfl_xor_sync(0xffffffffu, q, o);
        wn += __shfl_xor_sync(0xffffffffu, wn, o);
        ds += __shfl_xor_sync(0xffffffffu, ds, o);
    }
    if (lane == 0) { sh[0][warp] = q; sh[1][warp] = wn; sh[2][warp] = ds; }
    __syncthreads();

    __shared__ int s_last;
    if (tid == 0) {
        double bq = 0.0, bwn = 0.0, bds = 0.0;
#pragma unroll
        for (int i = 0; i < 8; i++) { bq += sh[0][i]; bwn += sh[1][i]; bds += sh[2][i]; }
        g_part[blockIdx.x][0] = bq;
        g_part[blockIdx.x][1] = bwn;
        g_part[blockIdx.x][2] = bds;
        __threadfence();
        unsigned t = atomicAdd(&g_ticket, 1u);
        s_last = (t == RED_BLOCKS - 1) ? 1 : 0;
    }
    __syncthreads();

    if (s_last && tid == 0) {
        double tq = 0.0, twn = 0.0, tds = 0.0;
#pragma unroll
        for (int i = 0; i < RED_BLOCKS; i++) {   // fixed order -> deterministic
            tq  += g_part[i][0];
            twn += g_part[i][1];
            tds += g_part[i][2];
        }
        const double LOG_2PI_D = 1.837877066409345483560659472811;
        double mean_q  = tq / (double)N_SAMP - log((double)K_COMP);
        double mean_wn = twn / (double)N_SAMP;
        double mean_d  = tds / (double)N_SAMP;
        double data_lp = -0.5 * 5.0 * mean_d
                       + (double)B_X * 0.5 * (log(5.0) - LOG_2PI_D);
        double prior   = -0.5 * mean_wn - 0.5 * (double)D_W * LOG_2PI_D;
        double kl      = mean_q - prior;
        out[0] = (float)(data_lp - kl);
        g_ticket = 0;                            // reset for next graph replay
    }
}

// ---------------- launch ----------------
extern "C" void kernel_launch(void* const* d_in, const int* in_sizes, int n_in,
                              void* d_out, int out_size) {
    const float* emp  = (const float*)d_in[0];
    const float* rhos = (const float*)d_in[1];
    const float* x    = (const float*)d_in[2];
    const float* y    = (const float*)d_in[3];
    const float* eps  = (const float*)d_in[4];
    const int*   idxs = (const int*)d_in[5];
    float* out = (float*)d_out;

    prep_all<<<32 + (K_COMP + NNB * 32 + 255) / 256, 256>>>(emp, rhos, eps, idxs);
    fused_main<<<LSE_BLOCKS + REG_BLOCKS, 256>>>(x, y);
    reduce_final<<<RED_BLOCKS, 256>>>(out);
}

// round 11
// speedup vs baseline: 1.5598x; 1.5598x over previous
#include <cuda_runtime.h>
#include <math.h>
#include <stdint.h>

#define K_COMP 8192
#define N_SAMP 8192
#define B_X    2048
#define D_W    13

#define LOG_2PI 1.8378770664093453f
#define L2E     1.4426950408889634f

#define NRB   (N_SAMP / 16)     // 512 row-blocks of 16 samples
#define NNB   (K_COMP / 8)      // 1024 col-blocks of 8 components
#define NC    16                // n-chunks (512 components each)
#define NB_PC (NNB / NC)        // 64 col-blocks per chunk

#define LSE_BLOCKS (NC * 64)            // 1024 (first in grid: longest blocks)
#define REG_BLOCKS (N_SAMP / 8)         // 1024 (8 warps/block, 1 sample/warp)
#define RED_BLOCKS 32

// smem: lse needs NB_PC*32*8 (Bfrag) + NB_PC*4*16 (gu) = 16KB + 4KB = 20KB
//       reg needs B_X*8 = 16KB.  Union = 20KB -> 4 blocks/SM = 80KB (safe).
#define SMEM_BYTES (NB_PC * 32 * 8 + NB_PC * 4 * 16)

// ---------------- scratch (no allocations allowed) ----------------
__device__ float  g_w16[N_SAMP * 16];     // fp32 w, padded k=13..15 = 0
__device__ float  g_wn[N_SAMP];           // ||w||^2 (fp32 exact)
__device__ float4 g_gu[K_COMP / 2];       // (g0,g1,u0,u1) per col-pair
__device__ uint4  g_Afrag[NRB * 32];      // per-lane A fragments (bf16x2 x4)
__device__ uint2  g_Bfrag[NNB * 32];      // per-lane B fragments (bf16x2 x2)
__device__ float  g_dsum[N_SAMP];         // sum_b (y_pred - y)^2
__device__ float  g_SP[NC][N_SAMP];       // per-chunk partial exp-sums
__device__ double g_part[RED_BLOCKS][3];  // per-block (q, wn, dsum) sums
__device__ unsigned g_ticket;             // last-block ticket (self-resetting)

__device__ __forceinline__ float tanh_fast(float x) {
    float r; asm("tanh.approx.f32 %0, %1;" : "=f"(r) : "f"(x)); return r;
}
__device__ __forceinline__ float exp2_fast(float x) {
    float r; asm("ex2.approx.f32 %0, %1;" : "=f"(r) : "f"(x)); return r;
}
// pack two f32 -> bf16x2, lo in low 16 bits
__device__ __forceinline__ unsigned packbf(float lo, float hi) {
    unsigned r; asm("cvt.rn.bf16x2.f32 %0, %1, %2;" : "=r"(r) : "f"(hi), "f"(lo)); return r;
}

// ---------------- kernel 1: ALL prep (block-range split) ----------------
__global__ __launch_bounds__(256) void prep_all(const float* __restrict__ emp,
                                                const float* __restrict__ rhos,
                                                const float* __restrict__ eps,
                                                const int* __restrict__ idxs) {
    if (blockIdx.x < 32) {
        __shared__ float sw[256][16];
        int tid = threadIdx.x;
        int s = blockIdx.x * 256 + tid;

        int idx = idxs[s];
        float rho = rhos[idx];
        float sd = (rho > 20.f) ? rho : log1pf(__expf(rho));
        float wn = 0.f;
#pragma unroll
        for (int d = 0; d < 16; d++) {
            float w = 0.f;
            if (d < D_W) w = fmaf(__ldg(&eps[s * D_W + d]), sd, __ldg(&emp[idx * D_W + d]));
            sw[tid][d] = w;
            g_w16[s * 16 + d] = w;
            wn = fmaf(w, w, wn);
        }
        g_wn[s] = wn;
        __syncthreads();

        // A fragments (m16n8k16 row.col A layout), 16 row-blocks per block
        int rb0 = blockIdx.x * 16;
#pragma unroll
        for (int h = 0; h < 2; h++) {
            int e = h * 256 + tid;             // 0..511
            int rbl = e >> 5;
            int lane = e & 31, gid = lane >> 2, tg = lane & 3;
            const float* w0 = sw[rbl * 16 + gid];
            const float* w8 = sw[rbl * 16 + gid + 8];
            int k0 = tg * 2;
            uint4 r;
            r.x = packbf(w0[k0], w0[k0 + 1]);
            r.y = packbf(w8[k0], w8[k0 + 1]);
            r.z = packbf(w0[k0 + 8], w0[k0 + 9]);
            r.w = packbf(w8[k0 + 8], w8[k0 + 9]);
            g_Afrag[(rb0 + rbl) * 32 + lane] = r;
        }
    } else {
        int tid = (blockIdx.x - 32) * 256 + threadIdx.x;
        if (tid < K_COMP) {
            int k = tid;
            float rho = rhos[k];
            float sd = (rho > 20.f) ? rho : log1pf(__expf(rho));   // softplus
            float var = sd * sd;
            float inv = 1.f / var;
            float en = 0.f;
#pragma unroll
            for (int d = 0; d < D_W; d++) {
                float v = __ldg(&emp[k * D_W + d]);
                en = fmaf(v, v, en);
            }
            float c = -0.5f * ((float)D_W * LOG_2PI + (float)D_W * logf(var));
            float g = L2E * inv;
            float u = L2E * (c - 0.5f * inv * en);
            float* gu = (float*)&g_gu[k >> 1];
            gu[(k & 1) + 0] = g;
            gu[(k & 1) + 2] = u;
        } else if (tid < K_COMP + NNB * 32) {
            // B fragments: m16n8k16 row.col B layout (n=gid, k=2tg.. / +8)
            int t2 = tid - K_COMP;
            int lane = t2 & 31, gid = lane >> 2, tg = lane & 3;
            int nb = t2 >> 5;
            int n = nb * 8 + gid;
            int k0 = tg * 2;
            float e0 = __ldg(&emp[n * D_W + k0]);
            float e1 = __ldg(&emp[n * D_W + k0 + 1]);
            float e2 = (k0 + 8 < D_W) ? __ldg(&emp[n * D_W + k0 + 8]) : 0.f;
            float e3 = (k0 + 9 < D_W) ? __ldg(&emp[n * D_W + k0 + 9]) : 0.f;
            uint2 r;
            r.x = packbf(e0, e1);
            r.y = packbf(e2, e3);
            g_Bfrag[t2] = r;
        }
    }
}

// ---------------- kernel 2: FUSED tensor-core lse + regression ----------------
// blocks [0, LSE_BLOCKS): mma + exp2 sum; 20KB chunk staged in smem once per
//   block (keeps 4 blocks/SM within default carveout — the 40KB version
//   halved occupancy and regressed).
// blocks [LSE_BLOCKS, +REG_BLOCKS): regression (MUFU tanh), smem reused for xy.
__global__ __launch_bounds__(256, 4) void fused_main(const float* __restrict__ x,
                                                     const float* __restrict__ y) {
    __shared__ __align__(16) unsigned char smem_raw[SMEM_BYTES];   // 20KB

    if (blockIdx.x < LSE_BLOCKS) {
        uint2*  sB  = (uint2*)smem_raw;                       // [NB_PC*32] 16KB
        float4* sGU = (float4*)(smem_raw + NB_PC * 32 * 8);   // [NB_PC*4]   4KB

        int bid = blockIdx.x;                   // 0..1023
        int tid = threadIdx.x;
        int wid = tid >> 5, lane = tid & 31;
        int gid = lane >> 2, tg = lane & 3;
        int chunk = bid >> 6;                   // 0..15
        int grp   = bid & 63;
        int rb = grp * 8 + wid;                 // 0..511
        int s0 = rb * 16;
        int nb0 = chunk * NB_PC;

        // stage chunk into smem (coalesced)
        for (int i = tid; i < NB_PC * 32; i += 256) sB[i] = g_Bfrag[nb0 * 32 + i];
        if (tid < NB_PC * 4) sGU[tid] = g_gu[nb0 * 4 + tid];

        uint4 af = g_Afrag[rb * 32 + lane];
        float hw0 = -0.5f * g_wn[s0 + gid];
        float hw8 = -0.5f * g_wn[s0 + gid + 8];
        float S0 = 0.f, S8 = 0.f;
        __syncthreads();

#pragma unroll 4
        for (int i = 0; i < NB_PC; i++) {
            uint2 bf = sB[i * 32 + lane];       // LDS.64, conflict-free
            float4 gu = sGU[i * 4 + tg];        // LDS.128, quad-broadcast
            float c0 = hw0, c1 = hw0, c2 = hw8, c3 = hw8;
            asm volatile(
                "mma.sync.aligned.m16n8k16.row.col.f32.bf16.bf16.f32 "
                "{%0,%1,%2,%3}, {%4,%5,%6,%7}, {%8,%9}, {%0,%1,%2,%3};"
                : "+f"(c0), "+f"(c1), "+f"(c2), "+f"(c3)
                : "r"(af.x), "r"(af.y), "r"(af.z), "r"(af.w),
                  "r"(bf.x), "r"(bf.y));
            // t = g*(dot - 0.5||w||^2) + u  (base-2, unshifted; always < 0)
            S0 += exp2_fast(fmaf(gu.x, c0, gu.z));
            S0 += exp2_fast(fmaf(gu.y, c1, gu.w));
            S8 += exp2_fast(fmaf(gu.x, c2, gu.z));
            S8 += exp2_fast(fmaf(gu.y, c3, gu.w));
        }

        S0 += __shfl_xor_sync(0xffffffffu, S0, 1);
        S0 += __shfl_xor_sync(0xffffffffu, S0, 2);
        S8 += __shfl_xor_sync(0xffffffffu, S8, 1);
        S8 += __shfl_xor_sync(0xffffffffu, S8, 2);
        if (tg == 0) {
            g_SP[chunk][s0 + gid]     = S0;
            g_SP[chunk][s0 + gid + 8] = S8;
        }
    } else {
        float2* sxy = (float2*)smem_raw;        // [B_X] = 16KB

        int bid = blockIdx.x - LSE_BLOCKS;      // 0..1023
        int tid = threadIdx.x;
        for (int i = tid; i < B_X; i += 256)
            sxy[i] = make_float2(x[i], y[i]);
        __syncthreads();

        int wid = tid >> 5, lane = tid & 31;
        int s = bid * 8 + wid;

        float wd = (lane < D_W) ? g_w16[s * 16 + lane] : 0.f;
        float p[D_W];
#pragma unroll
        for (int d = 0; d < D_W; d++) p[d] = __shfl_sync(0xffffffffu, wd, d);
        float w10 = p[0], w11 = p[1], b10 = p[2], b11 = p[3];
        float w200 = p[4], w201 = p[5], w210 = p[6], w211 = p[7];
        float b20 = p[8], b21 = p[9], w30 = p[10], w31 = p[11], b3 = p[12];

        float acc = 0.f;
#pragma unroll 8
        for (int t = 0; t < B_X / 32; t++) {
            float2 xy = sxy[t * 32 + lane];
            float h0 = tanh_fast(fmaf(w10, xy.x, b10));
            float h1 = tanh_fast(fmaf(w11, xy.x, b11));
            float z0 = tanh_fast(fmaf(w200, h0, fmaf(w201, h1, b20)));
            float z1 = tanh_fast(fmaf(w210, h0, fmaf(w211, h1, b21)));
            float yp = fmaf(w30, z0, fmaf(w31, z1, b3));
            float d = yp - xy.y;
            acc = fmaf(d, d, acc);
        }
#pragma unroll
        for (int o = 16; o; o >>= 1) acc += __shfl_xor_sync(0xffffffffu, acc, o);
        if (lane == 0) g_dsum[s] = acc;
    }
}

// ---------------- kernel 3: reduction + final (last-block pattern) ----------------
__global__ __launch_bounds__(256) void reduce_final(float* __restrict__ out) {
    __shared__ double sh[3][8];
    int tid = threadIdx.x;
    int s = blockIdx.x * 256 + tid;

    float S = 0.f;
#pragma unroll
    for (int c = 0; c < NC; c++) S += g_SP[c][s];
    double q  = (double)__logf(S);
    double wn = (double)g_wn[s];
    double ds = (double)g_dsum[s];

    int lane = tid & 31, warp = tid >> 5;
#pragma unroll
    for (int o = 16; o; o >>= 1) {
        q  += __shfl_xor_sync(0xffffffffu, q, o);
        wn += __shfl_xor_sync(0xffffffffu, wn, o);
        ds += __shfl_xor_sync(0xffffffffu, ds, o);
    }
    if (lane == 0) { sh[0][warp] = q; sh[1][warp] = wn; sh[2][warp] = ds; }
    __syncthreads();

    __shared__ int s_last;
    if (tid == 0) {
        double bq = 0.0, bwn = 0.0, bds = 0.0;
#pragma unroll
        for (int i = 0; i < 8; i++) { bq += sh[0][i]; bwn += sh[1][i]; bds += sh[2][i]; }
        g_part[blockIdx.x][0] = bq;
        g_part[blockIdx.x][1] = bwn;
        g_part[blockIdx.x][2] = bds;
        __threadfence();
        unsigned t = atomicAdd(&g_ticket, 1u);
        s_last = (t == RED_BLOCKS - 1) ? 1 : 0;
    }
    __syncthreads();

    if (s_last && tid == 0) {
        double tq = 0.0, twn = 0.0, tds = 0.0;
#pragma unroll
        for (int i = 0; i < RED_BLOCKS; i++) {   // fixed order -> deterministic
            tq  += g_part[i][0];
            twn += g_part[i][1];
            tds += g_part[i][2];
        }
        const double LOG_2PI_D = 1.837877066409345483560659472811;
        double mean_q  = tq / (double)N_SAMP - log((double)K_COMP);
        double mean_wn = twn / (double)N_SAMP;
        double mean_d  = tds / (double)N_SAMP;
        double data_lp = -0.5 * 5.0 * mean_d
                       + (double)B_X * 0.5 * (log(5.0) - LOG_2PI_D);
        double prior   = -0.5 * mean_wn - 0.5 * (double)D_W * LOG_2PI_D;
        double kl      = mean_q - prior;
        out[0] = (float)(data_lp - kl);
        g_ticket = 0;                            // reset for next graph replay
    }
}

// ---------------- launch ----------------
extern "C" void kernel_launch(void* const* d_in, const int* in_sizes, int n_in,
                              void* d_out, int out_size) {
    const float* emp  = (const float*)d_in[0];
    const float* rhos = (const float*)d_in[1];
    const float* x    = (const float*)d_in[2];
    const float* y    = (const float*)d_in[3];
    const float* eps  = (const float*)d_in[4];
    const int*   idxs = (const int*)d_in[5];
    float* out = (float*)d_out;

    prep_all<<<32 + (K_COMP + NNB * 32 + 255) / 256, 256>>>(emp, rhos, eps, idxs);
    fused_main<<<LSE_BLOCKS + REG_BLOCKS, 256>>>(x, y);
    reduce_final<<<RED_BLOCKS, 256>>>(out);
}